// round 12
// baseline (speedup 1.0000x reference)
#include <cuda_runtime.h>
#include <cuda_fp16.h>
#include <cstdint>

#define N_NODES 50000
#define N_EDGES 800000
#define F 128
#define NCLS 47

// ---------------- scratch (device globals; no allocation allowed) ----------------
__device__ int    g_deg[N_NODES];
__device__ int    g_row_ptr[N_NODES + 1];
__device__ int    g_cursor[N_NODES];
__device__ int    g_csr_src[N_EDGES];
__device__ __half g_xh[N_NODES * F];     // fp16 copy of x (gather path)
__device__ __half g_h1h[N_NODES * F];    // fp16 copy of h1 (gather path); dummy sink for h2
__device__ __half g_hn[N_NODES * F];     // neighbor mean (fp16)
__device__ float  g_h1[N_NODES * F];     // layer-0 output (fp32 self path)
__device__ float  g_h2[N_NODES * F];     // layer-1 output (fp32 self path)
__device__ __half g_q2[N_NODES * 64];    // layer-2 neighbor projection (fp16, 47 pad 64)

// =============================== helpers ====================================
__device__ __forceinline__ float tf32r(float x) {
    float y;
    asm("cvt.rna.tf32.f32 %0, %1;" : "=f"(y) : "f"(x));
    return y;
}

__device__ __forceinline__ void mma_tf32(float* c, uint32_t a0, uint32_t a1,
                                         uint32_t a2, uint32_t a3,
                                         uint32_t b0, uint32_t b1) {
    asm volatile(
        "mma.sync.aligned.m16n8k8.row.col.f32.tf32.tf32.f32 "
        "{%0,%1,%2,%3}, {%4,%5,%6,%7}, {%8,%9}, {%0,%1,%2,%3};"
        : "+f"(c[0]), "+f"(c[1]), "+f"(c[2]), "+f"(c[3])
        : "r"(a0), "r"(a1), "r"(a2), "r"(a3), "r"(b0), "r"(b1));
}

// ---------------- CSR build ----------------
__global__ void zero_deg_kernel() {
    int i = blockIdx.x * blockDim.x + threadIdx.x;
    if (i < N_NODES) g_deg[i] = 0;
}

__global__ void hist_kernel(const int* __restrict__ dst) {
    int e = blockIdx.x * blockDim.x + threadIdx.x;
    if (e < N_EDGES) atomicAdd(&g_deg[dst[e]], 1);
}

__global__ void scan_kernel() {
    __shared__ int sh[1024];
    const int T = 1024;
    int tid = threadIdx.x;
    const int CH = (N_NODES + T - 1) / T;
    int base = tid * CH;
    int local = 0;
    for (int i = 0; i < CH; i++) {
        int idx = base + i;
        if (idx < N_NODES) local += g_deg[idx];
    }
    sh[tid] = local;
    __syncthreads();
    for (int off = 1; off < T; off <<= 1) {
        int v = sh[tid];
        int add = (tid >= off) ? sh[tid - off] : 0;
        __syncthreads();
        sh[tid] = v + add;
        __syncthreads();
    }
    int run = sh[tid] - local;
    for (int i = 0; i < CH; i++) {
        int idx = base + i;
        if (idx < N_NODES) {
            g_row_ptr[idx] = run;
            g_cursor[idx]  = run;
            run += g_deg[idx];
        }
    }
    if (tid == T - 1) g_row_ptr[N_NODES] = sh[T - 1];
}

__global__ void csr_fill_kernel(const int* __restrict__ src, const int* __restrict__ dst) {
    int e = blockIdx.x * blockDim.x + threadIdx.x;
    if (e < N_EDGES) {
        int pos = atomicAdd(&g_cursor[dst[e]], 1);
        g_csr_src[pos] = src[e];
    }
}

// ---------------- x -> fp16 conversion ----------------
__global__ void x_to_half_kernel(const float* __restrict__ x) {
    int i = blockIdx.x * blockDim.x + threadIdx.x;  // per float4
    if (i < N_NODES * 32) {
        float4 v = ((const float4*)x)[i];
        __half2 a = __floats2half2_rn(v.x, v.y);
        __half2 b = __floats2half2_rn(v.z, v.w);
        uint2 o;
        o.x = *(uint32_t*)&a;
        o.y = *(uint32_t*)&b;
        ((uint2*)g_xh)[i] = o;
    }
}

// ------- 128-dim fp16 aggregation: warp per node, lane owns 4 halves, unroll-8 ----
__global__ void aggregate_kernel(const __half* __restrict__ h) {
    int gw   = (blockIdx.x * blockDim.x + threadIdx.x) >> 5;
    int lane = threadIdx.x & 31;
    if (gw >= N_NODES) return;
    const int node = gw;
    int s0 = g_row_ptr[node];
    int s1 = g_row_ptr[node + 1];
    float ax = 0.f, ay = 0.f, az = 0.f, aw = 0.f;
    const uint2* hv = (const uint2*)h;  // row = 32 uint2 (128 halves)
    int e = s0;
    for (; e + 7 < s1; e += 8) {
        int idx[8];
#pragma unroll
        for (int u = 0; u < 8; u++) idx[u] = g_csr_src[e + u];
#pragma unroll
        for (int u = 0; u < 8; u++) {
            uint2 p = hv[idx[u] * 32 + lane];
            __half2 p0 = *reinterpret_cast<const __half2*>(&p.x);
            __half2 p1 = *reinterpret_cast<const __half2*>(&p.y);
            float2 f0 = __half22float2(p0);
            float2 f1 = __half22float2(p1);
            ax += f0.x; ay += f0.y; az += f1.x; aw += f1.y;
        }
    }
    for (; e < s1; e++) {
        uint2 p = hv[g_csr_src[e] * 32 + lane];
        __half2 p0 = *reinterpret_cast<const __half2*>(&p.x);
        __half2 p1 = *reinterpret_cast<const __half2*>(&p.y);
        float2 f0 = __half22float2(p0);
        float2 f1 = __half22float2(p1);
        ax += f0.x; ay += f0.y; az += f1.x; aw += f1.y;
    }
    float inv = (s1 > s0) ? 1.0f / (float)(s1 - s0) : 0.0f;
    __half2 o0 = __floats2half2_rn(ax * inv, ay * inv);
    __half2 o1 = __floats2half2_rn(az * inv, aw * inv);
    uint2 o;
    o.x = *(uint32_t*)&o0;
    o.y = *(uint32_t*)&o1;
    ((uint2*)g_hn)[node * 32 + lane] = o;
}

// ------- 64-dim (padded-47) fp16 aggregation for layer 2: half-warp per node ------
__global__ void aggregate_out_kernel(const __half* __restrict__ q, float* __restrict__ out) {
    int gw   = (blockIdx.x * blockDim.x + threadIdx.x) >> 5;
    int lane = threadIdx.x & 31;
    int half = lane >> 4;
    int hl   = lane & 15;
    int node = gw * 2 + half;
    if (node >= N_NODES) return;
    int s0 = g_row_ptr[node];
    int s1 = g_row_ptr[node + 1];
    float ax = 0.f, ay = 0.f, az = 0.f, aw = 0.f;
    const uint2* qv = (const uint2*)q;  // row = 16 uint2
    int e = s0;
    for (; e + 7 < s1; e += 8) {
        int idx[8];
#pragma unroll
        for (int u = 0; u < 8; u++) idx[u] = g_csr_src[e + u];
#pragma unroll
        for (int u = 0; u < 8; u++) {
            uint2 p = qv[idx[u] * 16 + hl];
            __half2 p0 = *reinterpret_cast<const __half2*>(&p.x);
            __half2 p1 = *reinterpret_cast<const __half2*>(&p.y);
            float2 f0 = __half22float2(p0);
            float2 f1 = __half22float2(p1);
            ax += f0.x; ay += f0.y; az += f1.x; aw += f1.y;
        }
    }
    for (; e < s1; e++) {
        uint2 p = qv[g_csr_src[e] * 16 + hl];
        __half2 p0 = *reinterpret_cast<const __half2*>(&p.x);
        __half2 p1 = *reinterpret_cast<const __half2*>(&p.y);
        float2 f0 = __half22float2(p0);
        float2 f1 = __half22float2(p1);
        ax += f0.x; ay += f0.y; az += f1.x; aw += f1.y;
    }
    float inv = (s1 > s0) ? 1.0f / (float)(s1 - s0) : 0.0f;
    float vals[4] = {ax * inv, ay * inv, az * inv, aw * inv};
    int c0 = hl * 4;
#pragma unroll
    for (int i = 0; i < 4; i++) {
        int c = c0 + i;
        if (c < NCLS) out[(size_t)node * NCLS + c] += vals[i];
    }
}

// ============== mma.sync tf32 fused GEMM (layers 0/1) =============================
__global__ void __launch_bounds__(256, 1) sage_gemm_l01(
    const float* __restrict__ Ah, const __half* __restrict__ An,
    const float* __restrict__ Wself, const float* __restrict__ Wneigh,
    const float* __restrict__ bias, const float* __restrict__ gamma,
    const float* __restrict__ beta, float* __restrict__ out,
    __half* __restrict__ outh)
{
    constexpr int NPAD = 128, NTN = 16, NOUT = 128;
    extern __shared__ float smem[];
    float* Wsh    = smem;
    float* Ash    = smem + 256 * NPAD;
    float* bias_s = Ash + 128 * 128;
    float* g_s    = bias_s + NPAD;
    float* be_s   = g_s + NPAD;

    const int tid = threadIdx.x, wid = tid >> 5, lane = tid & 31;

    for (int i = tid; i < 256 * NPAD; i += 256) {
        int k = i / NPAD, n = i % NPAD;
        float w = (k < 128) ? Wself[k * NOUT + n] : Wneigh[(k - 128) * NOUT + n];
        Wsh[k * NPAD + (n ^ ((k & 3) << 3))] = tf32r(w);
    }
    for (int i = tid; i < NPAD; i += 256) {
        bias_s[i] = bias[i];
        g_s[i]    = gamma[i];
        be_s[i]   = beta[i];
    }
    __syncthreads();

    const int NT = (N_NODES + 127) / 128;
    const int ra   = wid * 16 + (lane >> 2);
    const int aswz = (ra & 7) << 2;
    const int bswz = (lane & 3) << 3;
    const int nb   = lane >> 2;

    for (int t = blockIdx.x; t < NT; t += gridDim.x) {
        const int row0 = t * 128;

        float acc[NTN][4];
#pragma unroll
        for (int j = 0; j < NTN; j++)
#pragma unroll
            for (int q = 0; q < 4; q++) acc[j][q] = 0.f;

#pragma unroll
        for (int half = 0; half < 2; half++) {
            if (half == 0) {
                for (int i = tid; i < 128 * 32; i += 256) {
                    int r = i >> 5, q = i & 31;
                    int row = row0 + r;
                    float4 v = make_float4(0.f, 0.f, 0.f, 0.f);
                    if (row < N_NODES) {
                        v = ((const float4*)(Ah + (size_t)row * F))[q];
                        v.x = tf32r(v.x); v.y = tf32r(v.y);
                        v.z = tf32r(v.z); v.w = tf32r(v.w);
                    }
                    ((float4*)Ash)[r * 32 + (q ^ (r & 7))] = v;
                }
            } else {
                for (int i = tid; i < 128 * 32; i += 256) {
                    int r = i >> 5, q = i & 31;
                    int row = row0 + r;
                    float4 v = make_float4(0.f, 0.f, 0.f, 0.f);
                    if (row < N_NODES) {
                        uint2 p = ((const uint2*)An)[row * 32 + q];
                        __half2 p0 = *reinterpret_cast<const __half2*>(&p.x);
                        __half2 p1 = *reinterpret_cast<const __half2*>(&p.y);
                        float2 f0 = __half22float2(p0);
                        float2 f1 = __half22float2(p1);
                        v.x = tf32r(f0.x); v.y = tf32r(f0.y);
                        v.z = tf32r(f1.x); v.w = tf32r(f1.y);
                    }
                    ((float4*)Ash)[r * 32 + (q ^ (r & 7))] = v;
                }
            }
            __syncthreads();

#pragma unroll
            for (int step = 0; step < 16; step++) {
                const int k0 = step * 8;
                const int ka = k0 + (lane & 3);
                uint32_t a0 = __float_as_uint(Ash[ra * 128 + (ka ^ aswz)]);
                uint32_t a1 = __float_as_uint(Ash[(ra + 8) * 128 + (ka ^ aswz)]);
                uint32_t a2 = __float_as_uint(Ash[ra * 128 + ((ka + 4) ^ aswz)]);
                uint32_t a3 = __float_as_uint(Ash[(ra + 8) * 128 + ((ka + 4) ^ aswz)]);
                const int kb = half * 128 + k0 + (lane & 3);
                const float* wrow0 = Wsh + kb * NPAD;
                const float* wrow1 = wrow0 + 4 * NPAD;
#pragma unroll
                for (int j = 0; j < NTN; j++) {
                    int csw = (j * 8 + nb) ^ bswz;
                    uint32_t b0 = __float_as_uint(wrow0[csw]);
                    uint32_t b1 = __float_as_uint(wrow1[csw]);
                    mma_tf32(acc[j], a0, a1, a2, a3, b0, b1);
                }
            }
            __syncthreads();
        }

#pragma unroll
        for (int h = 0; h < 2; h++) {
            const int row = row0 + wid * 16 + (lane >> 2) + h * 8;
            float v[2 * NTN];
#pragma unroll
            for (int j = 0; j < NTN; j++) {
                int c0 = j * 8 + 2 * (lane & 3);
                v[2 * j]     = acc[j][2 * h]     + bias_s[c0];
                v[2 * j + 1] = acc[j][2 * h + 1] + bias_s[c0 + 1];
            }
            float s = 0.f;
#pragma unroll
            for (int q = 0; q < 2 * NTN; q++) s += v[q];
            s += __shfl_xor_sync(0xffffffffu, s, 1);
            s += __shfl_xor_sync(0xffffffffu, s, 2);
            float mean = s * (1.0f / (float)NOUT);
            float qv = 0.f;
#pragma unroll
            for (int q = 0; q < 2 * NTN; q++) { float d = v[q] - mean; qv += d * d; }
            qv += __shfl_xor_sync(0xffffffffu, qv, 1);
            qv += __shfl_xor_sync(0xffffffffu, qv, 2);
            float rs = rsqrtf(qv * (1.0f / (float)NOUT) + 1e-5f);
#pragma unroll
            for (int j = 0; j < NTN; j++) {
                int c0 = j * 8 + 2 * (lane & 3);
                v[2 * j]     = fmaxf((v[2 * j]     - mean) * rs * g_s[c0]     + be_s[c0],     0.f);
                v[2 * j + 1] = fmaxf((v[2 * j + 1] - mean) * rs * g_s[c0 + 1] + be_s[c0 + 1], 0.f);
            }
            if (row < N_NODES) {
#pragma unroll
                for (int j = 0; j < NTN; j++) {
                    int c0 = j * 8 + 2 * (lane & 3);
                    *(float2*)(out + (size_t)row * NOUT + c0) = make_float2(v[2 * j], v[2 * j + 1]);
                    if (outh) {
                        __half2 hv2 = __floats2half2_rn(v[2 * j], v[2 * j + 1]);
                        *(__half2*)(outh + (size_t)row * NOUT + c0) = hv2;
                    }
                }
            }
        }
        __syncthreads();
    }
}

// ======== layer-2 GEMM: h2 @ [Ws2 | Wn2] (K=128, 94 cols padded to 96) ===========
__global__ void __launch_bounds__(256, 1) sage_gemm_out(
    const float* __restrict__ Ah,
    const float* __restrict__ Wself, const float* __restrict__ Wneigh,
    const float* __restrict__ bias,
    float* __restrict__ out, __half* __restrict__ q)
{
    constexpr int NPAD = 96, NTN = 12;
    extern __shared__ float smem[];
    float* Wsh    = smem;
    float* Ash    = smem + 128 * NPAD;
    float* bias_s = Ash + 128 * 128;

    const int tid = threadIdx.x, wid = tid >> 5, lane = tid & 31;

    for (int i = tid; i < 128 * NPAD; i += 256) {
        int k = i / NPAD, n = i % NPAD;
        float w = 0.f;
        if (n < NCLS)           w = Wself[k * NCLS + n];
        else if (n < 2 * NCLS)  w = Wneigh[k * NCLS + (n - NCLS)];
        Wsh[k * NPAD + (n ^ ((k & 3) << 3))] = tf32r(w);
    }
    for (int i = tid; i < NPAD; i += 256)
        bias_s[i] = (i < NCLS) ? bias[i] : 0.f;
    __syncthreads();

    const int NT = (N_NODES + 127) / 128;
    const int ra   = wid * 16 + (lane >> 2);
    const int aswz = (ra & 7) << 2;
    const int bswz = (lane & 3) << 3;
    const int nb   = lane >> 2;

    for (int t = blockIdx.x; t < NT; t += gridDim.x) {
        const int row0 = t * 128;

        float acc[NTN][4];
#pragma unroll
        for (int j = 0; j < NTN; j++)
#pragma unroll
            for (int w4 = 0; w4 < 4; w4++) acc[j][w4] = 0.f;

        for (int i = tid; i < 128 * 32; i += 256) {
            int r = i >> 5, qq = i & 31;
            int row = row0 + r;
            float4 v = make_float4(0.f, 0.f, 0.f, 0.f);
            if (row < N_NODES) {
                v = ((const float4*)(Ah + (size_t)row * F))[qq];
                v.x = tf32r(v.x); v.y = tf32r(v.y);
                v.z = tf32r(v.z); v.w = tf32r(v.w);
            }
            ((float4*)Ash)[r * 32 + (qq ^ (r & 7))] = v;
        }
        __syncthreads();

#pragma unroll
        for (int step = 0; step < 16; step++) {
            const int k0 = step * 8;
            const int ka = k0 + (lane & 3);
            uint32_t a0 = __float_as_uint(Ash[ra * 128 + (ka ^ aswz)]);
            uint32_t a1 = __float_as_uint(Ash[(ra + 8) * 128 + (ka ^ aswz)]);
            uint32_t a2 = __float_as_uint(Ash[ra * 128 + ((ka + 4) ^ aswz)]);
            uint32_t a3 = __float_as_uint(Ash[(ra + 8) * 128 + ((ka + 4) ^ aswz)]);
            const int kb = k0 + (lane & 3);
            const float* wrow0 = Wsh + kb * NPAD;
            const float* wrow1 = wrow0 + 4 * NPAD;
#pragma unroll
            for (int j = 0; j < NTN; j++) {
                int csw = (j * 8 + nb) ^ bswz;
                uint32_t b0 = __float_as_uint(wrow0[csw]);
                uint32_t b1 = __float_as_uint(wrow1[csw]);
                mma_tf32(acc[j], a0, a1, a2, a3, b0, b1);
            }
        }
        __syncthreads();

#pragma unroll
        for (int h = 0; h < 2; h++) {
            const int row = row0 + wid * 16 + (lane >> 2) + h * 8;
            if (row < N_NODES) {
#pragma unroll
                for (int j = 0; j < NTN; j++) {
                    int c0 = j * 8 + 2 * (lane & 3);
#pragma unroll
                    for (int u = 0; u < 2; u++) {
                        int c = c0 + u;
                        float vv = acc[j][2 * h + u] + bias_s[c];
                        if (c < NCLS)
                            out[(size_t)row * NCLS + c] = vv;
                        else
                            q[(size_t)row * 64 + (c - NCLS)] =
                                __float2half_rn((c < 2 * NCLS) ? vv : 0.f);
                    }
                }
            }
        }
        __syncthreads();
    }
}

// ---------------- launch ----------------
extern "C" void kernel_launch(void* const* d_in, const int* in_sizes, int n_in,
                              void* d_out, int out_size) {
    const float* x   = (const float*)d_in[0];
    const int*   src = (const int*)d_in[1];
    const int*   dst = (const int*)d_in[2];
    const float* ws0 = (const float*)d_in[3];
    const float* wn0 = (const float*)d_in[4];
    const float* b0  = (const float*)d_in[5];
    const float* gm0 = (const float*)d_in[6];
    const float* bt0 = (const float*)d_in[7];
    const float* ws1 = (const float*)d_in[8];
    const float* wn1 = (const float*)d_in[9];
    const float* b1  = (const float*)d_in[10];
    const float* gm1 = (const float*)d_in[11];
    const float* bt1 = (const float*)d_in[12];
    const float* ws2 = (const float*)d_in[13];
    const float* wn2 = (const float*)d_in[14];
    const float* b2  = (const float*)d_in[15];
    float* out = (float*)d_out;

    __half *xh, *h1h, *hn, *q2;
    float *h1, *h2;
    cudaGetSymbolAddress((void**)&xh,  g_xh);
    cudaGetSymbolAddress((void**)&h1h, g_h1h);
    cudaGetSymbolAddress((void**)&hn,  g_hn);
    cudaGetSymbolAddress((void**)&h1,  g_h1);
    cudaGetSymbolAddress((void**)&h2,  g_h2);
    cudaGetSymbolAddress((void**)&q2,  g_q2);

    const int SMEM_L01 = (256 * 128 + 128 * 128 + 3 * 128) * 4;  // 198144
    const int SMEM_L2  = (128 * 96 + 128 * 128 + 96) * 4;        // 115072
    cudaFuncSetAttribute(sage_gemm_l01,
                         cudaFuncAttributeMaxDynamicSharedMemorySize, SMEM_L01);
    cudaFuncSetAttribute(sage_gemm_out,
                         cudaFuncAttributeMaxDynamicSharedMemorySize, SMEM_L2);

    // x -> fp16 copy (gather path)
    x_to_half_kernel<<<(N_NODES * 32 + 255) / 256, 256>>>(x);

    // CSR build (reused by all 3 layers)
    zero_deg_kernel<<<(N_NODES + 255) / 256, 256>>>();
    hist_kernel<<<(N_EDGES + 255) / 256, 256>>>(dst);
    scan_kernel<<<1, 1024>>>();
    csr_fill_kernel<<<(N_EDGES + 255) / 256, 256>>>(src, dst);

    const int AGG_BLOCKS  = (N_NODES * 32 + 255) / 256;              // warp per node
    const int AGG2_BLOCKS = (((N_NODES + 1) / 2) * 32 + 255) / 256;  // half-warp per node

    // layer 0: fp16 h1 copy IS needed (layer-1 gather)
    aggregate_kernel<<<AGG_BLOCKS, 256>>>(xh);
    sage_gemm_l01<<<148, 256, SMEM_L01>>>(x, hn, ws0, wn0, b0, gm0, bt0, h1, h1h);
    // layer 1: no fp16 copy needed (layer 2 gathers q2, not h2)
    aggregate_kernel<<<AGG_BLOCKS, 256>>>(h1h);
    sage_gemm_l01<<<148, 256, SMEM_L01>>>(h1, hn, ws1, wn1, b1, gm1, bt1, h2, nullptr);
    // layer 2: project (self->out fp32, neigh->q2 fp16), then 47-dim aggregate into out
    sage_gemm_out<<<148, 256, SMEM_L2>>>(h2, ws2, wn2, b2, out, q2);
    aggregate_out_kernel<<<AGG2_BLOCKS, 256>>>(q2, out);
}

// round 13
// speedup vs baseline: 1.3590x; 1.3590x over previous
#include <cuda_runtime.h>
#include <cuda_bf16.h>
#include <cstdint>

#define N_NODES 50000
#define N_EDGES 800000
#define F 128
#define NCLS 47

#define SCAN_CHUNK 512
#define SCAN_BLOCKS ((N_NODES + SCAN_CHUNK - 1) / SCAN_CHUNK)  // 98

// ---------------- scratch (device globals; no allocation allowed) ----------------
__device__ int   g_deg[N_NODES];
__device__ int   g_row_ptr[N_NODES + 1];
__device__ int   g_cursor[N_NODES];
__device__ int   g_csr_src[N_EDGES];
__device__ int   g_bsum[SCAN_BLOCKS];
__device__ int   g_boff[SCAN_BLOCKS];
__device__ float g_hn[N_NODES * F];    // neighbor mean (layers 0/1)
__device__ float g_h1[N_NODES * F];    // layer-0 output
__device__ float g_h2[N_NODES * F];    // layer-1 output
__device__ float g_q2[N_NODES * 64];   // layer-2 neighbor projection (47 padded to 64)

// =============================== helpers ====================================
__device__ __forceinline__ float tf32r(float x) {
    float y;
    asm("cvt.rna.tf32.f32 %0, %1;" : "=f"(y) : "f"(x));
    return y;
}

__device__ __forceinline__ void mma_tf32(float* c, uint32_t a0, uint32_t a1,
                                         uint32_t a2, uint32_t a3,
                                         uint32_t b0, uint32_t b1) {
    asm volatile(
        "mma.sync.aligned.m16n8k8.row.col.f32.tf32.tf32.f32 "
        "{%0,%1,%2,%3}, {%4,%5,%6,%7}, {%8,%9}, {%0,%1,%2,%3};"
        : "+f"(c[0]), "+f"(c[1]), "+f"(c[2]), "+f"(c[3])
        : "r"(a0), "r"(a1), "r"(a2), "r"(a3), "r"(b0), "r"(b1));
}

// ---------------- CSR build ----------------
__global__ void zero_deg_kernel() {
    int i = blockIdx.x * blockDim.x + threadIdx.x;
    if (i < N_NODES) g_deg[i] = 0;
}

__global__ void hist_kernel(const int* __restrict__ dst) {
    int e = blockIdx.x * blockDim.x + threadIdx.x;
    if (e < N_EDGES) atomicAdd(&g_deg[dst[e]], 1);
}

// phase 1: per-block sums of 512-node chunks
__global__ void scan_phase1() {
    __shared__ int sh[256];
    int b = blockIdx.x, tid = threadIdx.x;
    int base = b * SCAN_CHUNK + tid * 2;
    int s = 0;
    if (base < N_NODES)     s += g_deg[base];
    if (base + 1 < N_NODES) s += g_deg[base + 1];
    sh[tid] = s;
    __syncthreads();
    for (int off = 128; off; off >>= 1) {
        if (tid < off) sh[tid] += sh[tid + off];
        __syncthreads();
    }
    if (tid == 0) g_bsum[b] = sh[0];
}

// phase 2: exclusive scan of the 98 block sums (single tiny block)
__global__ void scan_phase2() {
    __shared__ int sh[128];
    int tid = threadIdx.x;
    int v = (tid < SCAN_BLOCKS) ? g_bsum[tid] : 0;
    sh[tid] = v;
    __syncthreads();
    for (int off = 1; off < 128; off <<= 1) {
        int x = sh[tid];
        int a = (tid >= off) ? sh[tid - off] : 0;
        __syncthreads();
        sh[tid] = x + a;
        __syncthreads();
    }
    if (tid < SCAN_BLOCKS) g_boff[tid] = sh[tid] - v;
    if (tid == 0) g_row_ptr[N_NODES] = N_EDGES;  // total degree is a constant
}

// phase 3: in-block exclusive scan + offset -> row_ptr / cursor
__global__ void scan_phase3() {
    __shared__ int sh[256];
    int b = blockIdx.x, tid = threadIdx.x;
    int base = b * SCAN_CHUNK + tid * 2;
    int v0 = (base < N_NODES)     ? g_deg[base]     : 0;
    int v1 = (base + 1 < N_NODES) ? g_deg[base + 1] : 0;
    int s = v0 + v1;
    sh[tid] = s;
    __syncthreads();
    for (int off = 1; off < 256; off <<= 1) {
        int x = sh[tid];
        int a = (tid >= off) ? sh[tid - off] : 0;
        __syncthreads();
        sh[tid] = x + a;
        __syncthreads();
    }
    int excl = sh[tid] - s + g_boff[b];
    if (base < N_NODES)     { g_row_ptr[base]     = excl;      g_cursor[base]     = excl; }
    if (base + 1 < N_NODES) { g_row_ptr[base + 1] = excl + v0; g_cursor[base + 1] = excl + v0; }
}

__global__ void csr_fill_kernel(const int* __restrict__ src, const int* __restrict__ dst) {
    int e = blockIdx.x * blockDim.x + threadIdx.x;
    if (e < N_EDGES) {
        int pos = atomicAdd(&g_cursor[dst[e]], 1);
        g_csr_src[pos] = src[e];
    }
}

// ------- 128-dim aggregation: warp per node, lane owns one float4, unroll-4 -------
__global__ void aggregate_kernel(const float* __restrict__ h) {
    int gw   = (blockIdx.x * blockDim.x + threadIdx.x) >> 5;
    int lane = threadIdx.x & 31;
    if (gw >= N_NODES) return;
    const int node = gw;
    int s0 = g_row_ptr[node];
    int s1 = g_row_ptr[node + 1];
    float4 acc = make_float4(0.f, 0.f, 0.f, 0.f);
    const float4* hv = (const float4*)h;
    int e = s0;
    for (; e + 3 < s1; e += 4) {
        int i0 = g_csr_src[e];
        int i1 = g_csr_src[e + 1];
        int i2 = g_csr_src[e + 2];
        int i3 = g_csr_src[e + 3];
        float4 v0 = hv[i0 * 32 + lane];
        float4 v1 = hv[i1 * 32 + lane];
        float4 v2 = hv[i2 * 32 + lane];
        float4 v3 = hv[i3 * 32 + lane];
        acc.x += (v0.x + v1.x) + (v2.x + v3.x);
        acc.y += (v0.y + v1.y) + (v2.y + v3.y);
        acc.z += (v0.z + v1.z) + (v2.z + v3.z);
        acc.w += (v0.w + v1.w) + (v2.w + v3.w);
    }
    for (; e < s1; e++) {
        int i0 = g_csr_src[e];
        float4 v0 = hv[i0 * 32 + lane];
        acc.x += v0.x; acc.y += v0.y; acc.z += v0.z; acc.w += v0.w;
    }
    float inv = (s1 > s0) ? 1.0f / (float)(s1 - s0) : 0.0f;
    acc.x *= inv; acc.y *= inv; acc.z *= inv; acc.w *= inv;
    ((float4*)g_hn)[node * 32 + lane] = acc;
}

// ------- 64-dim (padded-47) aggregation for layer 2: half-warp per node ----------
__global__ void aggregate_out_kernel(const float* __restrict__ q, float* __restrict__ out) {
    int gw   = (blockIdx.x * blockDim.x + threadIdx.x) >> 5;
    int lane = threadIdx.x & 31;
    int half = lane >> 4;
    int hl   = lane & 15;
    int node = gw * 2 + half;
    if (node >= N_NODES) return;
    int s0 = g_row_ptr[node];
    int s1 = g_row_ptr[node + 1];
    float4 acc = make_float4(0.f, 0.f, 0.f, 0.f);
    const float4* qv = (const float4*)q;
    int e = s0;
    for (; e + 3 < s1; e += 4) {
        int i0 = g_csr_src[e];
        int i1 = g_csr_src[e + 1];
        int i2 = g_csr_src[e + 2];
        int i3 = g_csr_src[e + 3];
        float4 v0 = qv[i0 * 16 + hl];
        float4 v1 = qv[i1 * 16 + hl];
        float4 v2 = qv[i2 * 16 + hl];
        float4 v3 = qv[i3 * 16 + hl];
        acc.x += (v0.x + v1.x) + (v2.x + v3.x);
        acc.y += (v0.y + v1.y) + (v2.y + v3.y);
        acc.z += (v0.z + v1.z) + (v2.z + v3.z);
        acc.w += (v0.w + v1.w) + (v2.w + v3.w);
    }
    for (; e < s1; e++) {
        int i0 = g_csr_src[e];
        float4 v0 = qv[i0 * 16 + hl];
        acc.x += v0.x; acc.y += v0.y; acc.z += v0.z; acc.w += v0.w;
    }
    float inv = (s1 > s0) ? 1.0f / (float)(s1 - s0) : 0.0f;
    float vals[4] = {acc.x * inv, acc.y * inv, acc.z * inv, acc.w * inv};
    int c0 = hl * 4;
#pragma unroll
    for (int i = 0; i < 4; i++) {
        int c = c0 + i;
        if (c < NCLS) out[(size_t)node * NCLS + c] += vals[i];
    }
}

// ============== mma.sync tf32 fused GEMM:  [h | hn] @ [Wself;Wneigh] + epilogue ===
template <int NOUT, int NPAD, int NTN, bool DOLN>
__global__ void __launch_bounds__(256, 1) sage_gemm_mma(
    const float* __restrict__ Ah, const float* __restrict__ An,
    const float* __restrict__ Wself, const float* __restrict__ Wneigh,
    const float* __restrict__ bias, const float* __restrict__ gamma,
    const float* __restrict__ beta, float* __restrict__ out)
{
    extern __shared__ float smem[];
    float* Wsh    = smem;                       // 256 * NPAD
    float* Ash    = smem + 256 * NPAD;          // 128 * 128
    float* bias_s = Ash + 128 * 128;            // NPAD
    float* g_s    = bias_s + NPAD;              // NPAD
    float* be_s   = g_s + NPAD;                 // NPAD

    const int tid = threadIdx.x, wid = tid >> 5, lane = tid & 31;

    for (int i = tid; i < 256 * NPAD; i += 256) {
        int k = i / NPAD, n = i % NPAD;
        float w = 0.f;
        if (n < NOUT) w = (k < 128) ? Wself[k * NOUT + n] : Wneigh[(k - 128) * NOUT + n];
        Wsh[k * NPAD + (n ^ ((k & 3) << 3))] = tf32r(w);
    }
    for (int i = tid; i < NPAD; i += 256) {
        bias_s[i] = (i < NOUT) ? bias[i] : 0.f;
        if (DOLN) {
            g_s[i]  = (i < NOUT) ? gamma[i] : 0.f;
            be_s[i] = (i < NOUT) ? beta[i]  : 0.f;
        }
    }
    __syncthreads();

    const int NT = (N_NODES + 127) / 128;
    const int ra   = wid * 16 + (lane >> 2);
    const int aswz = (ra & 7) << 2;
    const int bswz = (lane & 3) << 3;
    const int nb   = lane >> 2;

    for (int t = blockIdx.x; t < NT; t += gridDim.x) {
        const int row0 = t * 128;

        float acc[NTN][4];
#pragma unroll
        for (int j = 0; j < NTN; j++)
#pragma unroll
            for (int q = 0; q < 4; q++) acc[j][q] = 0.f;

#pragma unroll
        for (int half = 0; half < 2; half++) {
            const float* srcp = half ? An : Ah;
            for (int i = tid; i < 128 * 32; i += 256) {
                int r = i >> 5, q = i & 31;
                int row = row0 + r;
                float4 v = make_float4(0.f, 0.f, 0.f, 0.f);
                if (row < N_NODES) {
                    v = ((const float4*)(srcp + (size_t)row * F))[q];
                    v.x = tf32r(v.x); v.y = tf32r(v.y);
                    v.z = tf32r(v.z); v.w = tf32r(v.w);
                }
                ((float4*)Ash)[r * 32 + (q ^ (r & 7))] = v;
            }
            __syncthreads();

#pragma unroll
            for (int step = 0; step < 16; step++) {
                const int k0 = step * 8;
                const int ka = k0 + (lane & 3);
                uint32_t a0 = __float_as_uint(Ash[ra * 128 + (ka ^ aswz)]);
                uint32_t a1 = __float_as_uint(Ash[(ra + 8) * 128 + (ka ^ aswz)]);
                uint32_t a2 = __float_as_uint(Ash[ra * 128 + ((ka + 4) ^ aswz)]);
                uint32_t a3 = __float_as_uint(Ash[(ra + 8) * 128 + ((ka + 4) ^ aswz)]);
                const int kb = half * 128 + k0 + (lane & 3);
                const float* wrow0 = Wsh + kb * NPAD;
                const float* wrow1 = wrow0 + 4 * NPAD;
#pragma unroll
                for (int j = 0; j < NTN; j++) {
                    int csw = (j * 8 + nb) ^ bswz;
                    uint32_t b0 = __float_as_uint(wrow0[csw]);
                    uint32_t b1 = __float_as_uint(wrow1[csw]);
                    mma_tf32(acc[j], a0, a1, a2, a3, b0, b1);
                }
            }
            __syncthreads();
        }

#pragma unroll
        for (int h = 0; h < 2; h++) {
            const int row = row0 + wid * 16 + (lane >> 2) + h * 8;
            float v[2 * NTN];
#pragma unroll
            for (int j = 0; j < NTN; j++) {
                int c0 = j * 8 + 2 * (lane & 3);
                v[2 * j]     = acc[j][2 * h]     + bias_s[c0];
                v[2 * j + 1] = acc[j][2 * h + 1] + bias_s[c0 + 1];
            }
            if (DOLN) {
                float s = 0.f;
#pragma unroll
                for (int q = 0; q < 2 * NTN; q++) s += v[q];
                s += __shfl_xor_sync(0xffffffffu, s, 1);
                s += __shfl_xor_sync(0xffffffffu, s, 2);
                float mean = s * (1.0f / (float)NOUT);
                float qv = 0.f;
#pragma unroll
                for (int q = 0; q < 2 * NTN; q++) { float d = v[q] - mean; qv += d * d; }
                qv += __shfl_xor_sync(0xffffffffu, qv, 1);
                qv += __shfl_xor_sync(0xffffffffu, qv, 2);
                float rs = rsqrtf(qv * (1.0f / (float)NOUT) + 1e-5f);
#pragma unroll
                for (int j = 0; j < NTN; j++) {
                    int c0 = j * 8 + 2 * (lane & 3);
                    v[2 * j]     = fmaxf((v[2 * j]     - mean) * rs * g_s[c0]     + be_s[c0],     0.f);
                    v[2 * j + 1] = fmaxf((v[2 * j + 1] - mean) * rs * g_s[c0 + 1] + be_s[c0 + 1], 0.f);
                }
            }
            if (row < N_NODES) {
#pragma unroll
                for (int j = 0; j < NTN; j++) {
                    int c0 = j * 8 + 2 * (lane & 3);
                    if (c0 + 1 < NOUT)
                        *(float2*)(out + (size_t)row * NOUT + c0) = make_float2(v[2 * j], v[2 * j + 1]);
                    else if (c0 < NOUT)
                        out[(size_t)row * NOUT + c0] = v[2 * j];
                }
            }
        }
        __syncthreads();
    }
}

// ======== layer-2 GEMM: h2 @ [Ws2 | Wn2] (K=128, 94 cols padded to 96) ===========
__global__ void __launch_bounds__(256, 1) sage_gemm_out(
    const float* __restrict__ Ah,
    const float* __restrict__ Wself, const float* __restrict__ Wneigh,
    const float* __restrict__ bias,
    float* __restrict__ out, float* __restrict__ q)
{
    constexpr int NPAD = 96, NTN = 12;
    extern __shared__ float smem[];
    float* Wsh    = smem;                 // 128 * 96
    float* Ash    = smem + 128 * NPAD;    // 128 * 128
    float* bias_s = Ash + 128 * 128;      // 96

    const int tid = threadIdx.x, wid = tid >> 5, lane = tid & 31;

    for (int i = tid; i < 128 * NPAD; i += 256) {
        int k = i / NPAD, n = i % NPAD;
        float w = 0.f;
        if (n < NCLS)           w = Wself[k * NCLS + n];
        else if (n < 2 * NCLS)  w = Wneigh[k * NCLS + (n - NCLS)];
        Wsh[k * NPAD + (n ^ ((k & 3) << 3))] = tf32r(w);
    }
    for (int i = tid; i < NPAD; i += 256)
        bias_s[i] = (i < NCLS) ? bias[i] : 0.f;
    __syncthreads();

    const int NT = (N_NODES + 127) / 128;
    const int ra   = wid * 16 + (lane >> 2);
    const int aswz = (ra & 7) << 2;
    const int bswz = (lane & 3) << 3;
    const int nb   = lane >> 2;

    for (int t = blockIdx.x; t < NT; t += gridDim.x) {
        const int row0 = t * 128;

        float acc[NTN][4];
#pragma unroll
        for (int j = 0; j < NTN; j++)
#pragma unroll
            for (int w4 = 0; w4 < 4; w4++) acc[j][w4] = 0.f;

        for (int i = tid; i < 128 * 32; i += 256) {
            int r = i >> 5, qq = i & 31;
            int row = row0 + r;
            float4 v = make_float4(0.f, 0.f, 0.f, 0.f);
            if (row < N_NODES) {
                v = ((const float4*)(Ah + (size_t)row * F))[qq];
                v.x = tf32r(v.x); v.y = tf32r(v.y);
                v.z = tf32r(v.z); v.w = tf32r(v.w);
            }
            ((float4*)Ash)[r * 32 + (qq ^ (r & 7))] = v;
        }
        __syncthreads();

#pragma unroll
        for (int step = 0; step < 16; step++) {
            const int k0 = step * 8;
            const int ka = k0 + (lane & 3);
            uint32_t a0 = __float_as_uint(Ash[ra * 128 + (ka ^ aswz)]);
            uint32_t a1 = __float_as_uint(Ash[(ra + 8) * 128 + (ka ^ aswz)]);
            uint32_t a2 = __float_as_uint(Ash[ra * 128 + ((ka + 4) ^ aswz)]);
            uint32_t a3 = __float_as_uint(Ash[(ra + 8) * 128 + ((ka + 4) ^ aswz)]);
            const int kb = k0 + (lane & 3);
            const float* wrow0 = Wsh + kb * NPAD;
            const float* wrow1 = wrow0 + 4 * NPAD;
#pragma unroll
            for (int j = 0; j < NTN; j++) {
                int csw = (j * 8 + nb) ^ bswz;
                uint32_t b0 = __float_as_uint(wrow0[csw]);
                uint32_t b1 = __float_as_uint(wrow1[csw]);
                mma_tf32(acc[j], a0, a1, a2, a3, b0, b1);
            }
        }
        __syncthreads();

#pragma unroll
        for (int h = 0; h < 2; h++) {
            const int row = row0 + wid * 16 + (lane >> 2) + h * 8;
            if (row < N_NODES) {
#pragma unroll
                for (int j = 0; j < NTN; j++) {
                    int c0 = j * 8 + 2 * (lane & 3);
#pragma unroll
                    for (int u = 0; u < 2; u++) {
                        int c = c0 + u;
                        float vv = acc[j][2 * h + u] + bias_s[c];
                        if (c < NCLS)
                            out[(size_t)row * NCLS + c] = vv;
                        else if (c < 2 * NCLS)
                            q[(size_t)row * 64 + (c - NCLS)] = vv;
                    }
                }
            }
        }
        __syncthreads();
    }
}

// ---------------- launch ----------------
extern "C" void kernel_launch(void* const* d_in, const int* in_sizes, int n_in,
                              void* d_out, int out_size) {
    const float* x   = (const float*)d_in[0];
    const int*   src = (const int*)d_in[1];
    const int*   dst = (const int*)d_in[2];
    const float* ws0 = (const float*)d_in[3];
    const float* wn0 = (const float*)d_in[4];
    const float* b0  = (const float*)d_in[5];
    const float* gm0 = (const float*)d_in[6];
    const float* bt0 = (const float*)d_in[7];
    const float* ws1 = (const float*)d_in[8];
    const float* wn1 = (const float*)d_in[9];
    const float* b1  = (const float*)d_in[10];
    const float* gm1 = (const float*)d_in[11];
    const float* bt1 = (const float*)d_in[12];
    const float* ws2 = (const float*)d_in[13];
    const float* wn2 = (const float*)d_in[14];
    const float* b2  = (const float*)d_in[15];
    float* out = (float*)d_out;

    float *hn, *h1, *h2, *q2;
    cudaGetSymbolAddress((void**)&hn, g_hn);
    cudaGetSymbolAddress((void**)&h1, g_h1);
    cudaGetSymbolAddress((void**)&h2, g_h2);
    cudaGetSymbolAddress((void**)&q2, g_q2);

    const int SMEM_L01 = (256 * 128 + 128 * 128 + 3 * 128) * 4;  // 198144
    const int SMEM_L2  = (128 * 96 + 128 * 128 + 96) * 4;        // 115072
    cudaFuncSetAttribute(sage_gemm_mma<128, 128, 16, true>,
                         cudaFuncAttributeMaxDynamicSharedMemorySize, SMEM_L01);
    cudaFuncSetAttribute(sage_gemm_out,
                         cudaFuncAttributeMaxDynamicSharedMemorySize, SMEM_L2);

    // CSR build (reused by all 3 layers); parallel 3-phase scan
    zero_deg_kernel<<<(N_NODES + 255) / 256, 256>>>();
    hist_kernel<<<(N_EDGES + 255) / 256, 256>>>(dst);
    scan_phase1<<<SCAN_BLOCKS, 256>>>();
    scan_phase2<<<1, 128>>>();
    scan_phase3<<<SCAN_BLOCKS, 256>>>();
    csr_fill_kernel<<<(N_EDGES + 255) / 256, 256>>>(src, dst);

    const int AGG_BLOCKS  = (N_NODES * 32 + 255) / 256;              // warp per node
    const int AGG2_BLOCKS = (((N_NODES + 1) / 2) * 32 + 255) / 256;  // half-warp per node

    // layer 0
    aggregate_kernel<<<AGG_BLOCKS, 256>>>(x);
    sage_gemm_mma<128, 128, 16, true><<<148, 256, SMEM_L01>>>(x, hn, ws0, wn0, b0, gm0, bt0, h1);
    // layer 1
    aggregate_kernel<<<AGG_BLOCKS, 256>>>(h1);
    sage_gemm_mma<128, 128, 16, true><<<148, 256, SMEM_L01>>>(h1, hn, ws1, wn1, b1, gm1, bt1, h2);
    // layer 2: project first (self->out, neigh->q2), then 47-dim aggregate adds into out
    sage_gemm_out<<<148, 256, SMEM_L2>>>(h2, ws2, wn2, b2, out, q2);
    aggregate_out_kernel<<<AGG2_BLOCKS, 256>>>(q2, out);
}